// round 13
// baseline (speedup 1.0000x reference)
#include <cuda_runtime.h>
#include <math.h>
#include <stdint.h>

#define NSLOT 9
#define DD    64
#define TILE  128   // points per block
#define BLK   128   // threads per block

typedef unsigned long long u64;

// ---------------- packed f32x2 helpers ----------------
__device__ __forceinline__ u64 ffma2(u64 a, u64 b, u64 c) {
    u64 d;
    asm("fma.rn.f32x2 %0, %1, %2, %3;" : "=l"(d) : "l"(a), "l"(b), "l"(c));
    return d;
}
__device__ __forceinline__ u64 pack2(float x, float y) {
    u64 r; asm("mov.b64 %0, {%1, %2};" : "=l"(r) : "f"(x), "f"(y)); return r;
}
__device__ __forceinline__ u64 pack2dup(float x) {
    u64 r; asm("mov.b64 %0, {%1, %1};" : "=l"(r) : "f"(x)); return r;
}
__device__ __forceinline__ void unpack2(u64 v, float &x, float &y) {
    asm("mov.b64 {%0, %1}, %2;" : "=f"(x), "=f"(y) : "l"(v));
}
__device__ __forceinline__ void lds128(u64 &lo, u64 &hi, const void* p) {
    unsigned s = (unsigned)__cvta_generic_to_shared(p);
    asm("ld.shared.v2.b64 {%0, %1}, [%2];" : "=l"(lo), "=l"(hi) : "r"(s));
}

// ---------------- precomputed per-batch tables ----------------
__device__ float g_ck[2][NSLOT][DD];   // SCALE * Wq^T k_j
__device__ float g_c0[2][NSLOT];       // SCALE * Wq_b . k_j
__device__ float g_M [2][NSLOT][DD];   // slots_full[j] @ out_w^T
__device__ float g_sscale;             // exp(density_scale)

// grid = (NSLOT, B), block = 256 : 4-way split of the 64-term reductions
__global__ void __launch_bounds__(256)
precompute_kernel(const float* __restrict__ slots,
                  const float* __restrict__ empty_slot,
                  const float* __restrict__ Wq_w,
                  const float* __restrict__ Wq_b,
                  const float* __restrict__ Wk_w,
                  const float* __restrict__ Wk_b,
                  const float* __restrict__ out_w,
                  const float* __restrict__ density_scale)
{
    const int j    = blockIdx.x;
    const int b    = blockIdx.y;
    const int tid  = threadIdx.x;
    const int d    = tid & 63;
    const int part = tid >> 6;            // 0..3
    __shared__ float sf[DD];
    __shared__ float kv[DD];
    __shared__ float pK[4][DD];
    __shared__ float pM[4][DD];

    if (tid < DD)
        sf[tid] = (j == 0) ? empty_slot[tid]
                           : slots[((size_t)b * 8 + (j - 1)) * DD + tid];
    __syncthreads();

    {
        const float4* wk4 = (const float4*)(Wk_w  + (size_t)d * DD) + part * 4;
        const float4* ow4 = (const float4*)(out_w + (size_t)d * DD) + part * 4;
        const float4* sf4 = (const float4*)sf + part * 4;
        float aK = 0.f, aM = 0.f;
        #pragma unroll
        for (int c = 0; c < 4; ++c) {
            float4 s4 = sf4[c], k4 = wk4[c], o4 = ow4[c];
            aK = fmaf(s4.x, k4.x, aK); aK = fmaf(s4.y, k4.y, aK);
            aK = fmaf(s4.z, k4.z, aK); aK = fmaf(s4.w, k4.w, aK);
            aM = fmaf(s4.x, o4.x, aM); aM = fmaf(s4.y, o4.y, aM);
            aM = fmaf(s4.z, o4.z, aM); aM = fmaf(s4.w, o4.w, aM);
        }
        pK[part][d] = aK;
        pM[part][d] = aM;
    }
    __syncthreads();
    if (part == 0) {
        kv[d]        = Wk_b[d] + pK[0][d] + pK[1][d] + pK[2][d] + pK[3][d];
        g_M[b][j][d] = pM[0][d] + pM[1][d] + pM[2][d] + pM[3][d];
    }
    __syncthreads();

    {
        float a = 0.f;
        const int dd0 = part * 16;
        #pragma unroll
        for (int k = 0; k < 16; ++k)
            a = fmaf(Wq_w[(size_t)(dd0 + k) * DD + d], kv[dd0 + k], a);
        pK[part][d] = a;
    }
    __syncthreads();
    if (part == 0)
        g_ck[b][j][d] = 0.125f * (pK[0][d] + pK[1][d] + pK[2][d] + pK[3][d]);
    if (tid == 64) {
        float a = 0.f;
        #pragma unroll 8
        for (int dd = 0; dd < DD; ++dd)
            a = fmaf(Wq_b[dd], kv[dd], a);
        g_c0[b][j] = a * 0.125f;
    }
    if (b == 0 && j == 0 && tid == 0) g_sscale = expf(density_scale[0]);
}

// ============ kernel 1: logits + softmax -> w (global), sigma ============
__global__ void __launch_bounds__(BLK, 6)
logits_kernel(const float* __restrict__ x,
              const float* __restrict__ coor,
              float* __restrict__ wout,
              float* __restrict__ sig,
              int Npts)
{
    __shared__ float4 xs4[TILE * 16];          // 32 KB (aliased as wpack later)
    __shared__ float4 sCK4[NSLOT * 16];        // 2.25 KB
    __shared__ float  sC0[NSLOT];
    __shared__ float  sScale;

    float* wpack = (float*)xs4;                // packed [pt*9 + j], 4.5 KB alias

    const int b     = blockIdx.y;
    const int t     = threadIdx.x;
    const int tile0 = blockIdx.x * TILE;
    const int valid = min(TILE, Npts - tile0);
    const size_t base = (size_t)b * Npts + tile0;

    // coor prefetch (hidden behind staging)
    float cx = 0.f, cy = 0.f, cz = 0.f;
    if (t < valid) {
        const float* cp = coor + (base + t) * 3;
        cx = cp[0]; cy = cp[1]; cz = cp[2];
    }

    {
        const float4* gck = (const float4*)&g_ck[b][0][0];
        for (int i = t; i < NSLOT * 16; i += BLK) sCK4[i] = gck[i];
        if (t < NSLOT) sC0[t] = g_c0[b][t];
        if (t == 0)    sScale = g_sscale;
    }

    // ---- phase A: stage x tile (coalesced LDG, swizzled STS) ----
    {
        const float4* gx = (const float4*)(x + base * DD);
        #pragma unroll
        for (int kk = 0; kk < 16; ++kk) {
            int i   = kk * BLK + t;
            int row = i >> 4, ch = i & 15;
            if (row < valid)
                xs4[(row << 4) | (ch ^ (row & 7))] = gx[i];
        }
    }
    __syncthreads();

    // ---- phase B: logits + softmax, 1 point/thread ----
    float wv[NSLOT];
    float sg = 0.f;
    const bool active = (t < valid);
    if (active) {
        u64 acc[NSLOT];
        #pragma unroll
        for (int j = 0; j < NSLOT; ++j) acc[j] = 0ull;

        const float4* xr = &xs4[t << 4];
        const int sw = t & 7;
        #pragma unroll
        for (int c = 0; c < 16; ++c) {
            u64 xlo, xhi;
            lds128(xlo, xhi, &xr[c ^ sw]);
            #pragma unroll
            for (int j = 0; j < NSLOT; ++j) {
                u64 clo, chi;
                lds128(clo, chi, &sCK4[j * 16 + c]);
                acc[j] = ffma2(xlo, clo, acc[j]);
                acc[j] = ffma2(xhi, chi, acc[j]);
            }
        }
        float lg[NSLOT];
        #pragma unroll
        for (int j = 0; j < NSLOT; ++j) {
            float lo, hi; unpack2(acc[j], lo, hi);
            lg[j] = lo + hi + sC0[j];
        }

        bool oob = (fabsf(cx) > 1.0f) || (fabsf(cy) > 1.0f) || (fabsf(cz) > 1.0f);
        const int kmax = oob ? 2 : NSLOT;

        float m = fmaxf(lg[0], lg[1]);
        if (!oob) {
            #pragma unroll
            for (int j = 2; j < NSLOT; ++j) m = fmaxf(m, lg[j]);
        }
        float sum = 0.f;
        #pragma unroll
        for (int j = 0; j < NSLOT; ++j) {
            float e = (j < kmax) ? __expf(lg[j] - m) : 0.f;
            wv[j] = e; sum += e;
        }
        const float inv = __frcp_rn(sum);
        #pragma unroll
        for (int j = 1; j < NSLOT; ++j)
            sg = fmaf(fmaxf(lg[j], 0.f), wv[j], sg);
        sg *= inv * sScale;
        #pragma unroll
        for (int j = 0; j < NSLOT; ++j) wv[j] *= inv;
    }
    __syncthreads();            // xs reads done -> alias safe

    if (active) {
        sig[base + t] = sg;
        #pragma unroll
        for (int j = 0; j < NSLOT; ++j)        // stride-9, gcd(9,32)=1: conflict-free
            wpack[t * NSLOT + j] = wv[j];
    }
    __syncthreads();

    // ---- coalesced w writeout ----
    {
        float* gw = wout + base * (size_t)NSLOT;
        if (valid == TILE) {
            const float4* wp4 = (const float4*)wpack;   // 288 float4
            float4* gw4 = (float4*)gw;                  // base*9*4 % 16 == 0
            #pragma unroll
            for (int i = t; i < TILE * NSLOT / 4; i += BLK) gw4[i] = wp4[i];
        } else {
            for (int i = t; i < valid * NSLOT; i += BLK) gw[i] = wpack[i];
        }
    }
}

// ============ kernel 2: xo = w @ M + out_b (streaming) ============
__global__ void __launch_bounds__(BLK)
out_kernel(const float* __restrict__ wout,
           float* __restrict__ xo,
           const float* __restrict__ out_b,
           int Npts)
{
    __shared__ float wsh[TILE * 12];           // stride-12 padded, 6 KB

    const int b     = blockIdx.y;
    const int t     = threadIdx.x;
    const int tile0 = blockIdx.x * TILE;
    const int valid = min(TILE, Npts - tile0);
    const size_t base = (size_t)b * Npts + tile0;

    // stage w: coalesced global read -> stride-12 shared
    {
        const float* gw = wout + base * (size_t)NSLOT;
        for (int i = t; i < valid * NSLOT; i += BLK) {
            int pt = i / NSLOT, j = i - pt * NSLOT;
            wsh[pt * 12 + j] = gw[i];
        }
    }

    const int g  = t >> 4;     // group of 16 points
    const int ch = t & 15;     // f4 chunk of the 64-float row
    u64 Mlo[NSLOT], Mhi[NSLOT];
    #pragma unroll
    for (int j = 0; j < NSLOT; ++j) {
        float4 mv = ((const float4*)&g_M[b][j][0])[ch];
        Mlo[j] = pack2(mv.x, mv.y);
        Mhi[j] = pack2(mv.z, mv.w);
    }
    float4 obv = ((const float4*)out_b)[ch];
    const u64 oblo = pack2(obv.x, obv.y), obhi = pack2(obv.z, obv.w);
    __syncthreads();

    float4* go = (float4*)(xo + base * DD);
    #pragma unroll 4
    for (int i = 0; i < 16; ++i) {
        int pt = g * 16 + i;
        if (pt < valid) {
            const float* wp = &wsh[pt * 12];
            u64 w01, w23, w45, w67;
            lds128(w01, w23, wp);
            lds128(w45, w67, wp + 4);
            float w0,w1,w2,w3,w4,w5,w6,w7;
            unpack2(w01, w0, w1); unpack2(w23, w2, w3);
            unpack2(w45, w4, w5); unpack2(w67, w6, w7);
            float w8 = wp[8];
            float wreg[NSLOT] = {w0,w1,w2,w3,w4,w5,w6,w7,w8};

            u64 olo = oblo, ohi = obhi;
            #pragma unroll
            for (int j = 0; j < NSLOT; ++j) {
                u64 wj = pack2dup(wreg[j]);
                olo = ffma2(wj, Mlo[j], olo);
                ohi = ffma2(wj, Mhi[j], ohi);
            }
            float4 o;
            unpack2(olo, o.x, o.y);
            unpack2(ohi, o.z, o.w);
            go[pt * 16 + ch] = o;             // lanes 0-15 one contiguous row
        }
    }
}

extern "C" void kernel_launch(void* const* d_in, const int* in_sizes, int n_in,
                              void* d_out, int out_size)
{
    const float* point_feats   = (const float*)d_in[0];
    // d_in[1] = points_emb (unused by the scored block)
    const float* slots         = (const float*)d_in[2];
    const float* coor          = (const float*)d_in[3];
    const float* empty_slot    = (const float*)d_in[4];
    const float* Wq_w          = (const float*)d_in[5];
    const float* Wq_b          = (const float*)d_in[6];
    const float* Wk_w          = (const float*)d_in[7];
    const float* Wk_b          = (const float*)d_in[8];
    const float* out_w         = (const float*)d_in[9];
    const float* out_b         = (const float*)d_in[10];
    const float* density_scale = (const float*)d_in[11];

    const int B    = in_sizes[2] / (8 * 64);      // slots: [B, 8, 64]
    const int Npts = in_sizes[0] / (B * 64);      // point_feats: [B, N, 64]

    float* xo   = (float*)d_out;                                  // [B, N, 64]
    float* wout = xo + (size_t)B * Npts * 64;                     // [B, N, 9]
    float* sg   = wout + (size_t)B * Npts * 9;                    // [B, N]

    dim3 pgrid(NSLOT, B);
    precompute_kernel<<<pgrid, 256>>>(slots, empty_slot, Wq_w, Wq_b,
                                      Wk_w, Wk_b, out_w, density_scale);

    dim3 grid((Npts + TILE - 1) / TILE, B);
    logits_kernel<<<grid, BLK>>>(point_feats, coor, wout, sg, Npts);
    out_kernel<<<grid, BLK>>>(wout, xo, out_b, Npts);
}

// round 14
// speedup vs baseline: 1.0638x; 1.0638x over previous
#include <cuda_runtime.h>
#include <math.h>
#include <stdint.h>

#define NSLOT 9
#define DD    64
#define TILE  128   // points per block
#define BLK   128   // threads per block

typedef unsigned long long u64;

// ---------------- packed f32x2 helpers ----------------
__device__ __forceinline__ u64 ffma2(u64 a, u64 b, u64 c) {
    u64 d;
    asm("fma.rn.f32x2 %0, %1, %2, %3;" : "=l"(d) : "l"(a), "l"(b), "l"(c));
    return d;
}
__device__ __forceinline__ u64 pack2(float x, float y) {
    u64 r; asm("mov.b64 %0, {%1, %2};" : "=l"(r) : "f"(x), "f"(y)); return r;
}
__device__ __forceinline__ u64 pack2dup(float x) {
    u64 r; asm("mov.b64 %0, {%1, %1};" : "=l"(r) : "f"(x)); return r;
}
__device__ __forceinline__ void unpack2(u64 v, float &x, float &y) {
    asm("mov.b64 {%0, %1}, %2;" : "=f"(x), "=f"(y) : "l"(v));
}
__device__ __forceinline__ void lds128(u64 &lo, u64 &hi, const void* p) {
    unsigned s = (unsigned)__cvta_generic_to_shared(p);
    asm("ld.shared.v2.b64 {%0, %1}, [%2];" : "=l"(lo), "=l"(hi) : "r"(s));
}

// ---------------- precomputed per-batch tables ----------------
__device__ float g_ck[2][NSLOT][DD];   // SCALE * Wq^T k_j
__device__ float g_c0[2][NSLOT];       // SCALE * Wq_b . k_j
__device__ float g_M [2][NSLOT][DD];   // slots_full[j] @ out_w^T
__device__ float g_sscale;             // exp(density_scale)

// grid = (NSLOT, B), block = 256 : 4-way split of the 64-term reductions
__global__ void __launch_bounds__(256)
precompute_kernel(const float* __restrict__ slots,
                  const float* __restrict__ empty_slot,
                  const float* __restrict__ Wq_w,
                  const float* __restrict__ Wq_b,
                  const float* __restrict__ Wk_w,
                  const float* __restrict__ Wk_b,
                  const float* __restrict__ out_w,
                  const float* __restrict__ density_scale)
{
    const int j    = blockIdx.x;
    const int b    = blockIdx.y;
    const int tid  = threadIdx.x;
    const int d    = tid & 63;
    const int part = tid >> 6;            // 0..3
    __shared__ float sf[DD];
    __shared__ float kv[DD];
    __shared__ float pK[4][DD];
    __shared__ float pM[4][DD];

    if (tid < DD)
        sf[tid] = (j == 0) ? empty_slot[tid]
                           : slots[((size_t)b * 8 + (j - 1)) * DD + tid];
    __syncthreads();

    {
        const float4* wk4 = (const float4*)(Wk_w  + (size_t)d * DD) + part * 4;
        const float4* ow4 = (const float4*)(out_w + (size_t)d * DD) + part * 4;
        const float4* sf4 = (const float4*)sf + part * 4;
        float aK = 0.f, aM = 0.f;
        #pragma unroll
        for (int c = 0; c < 4; ++c) {
            float4 s4 = sf4[c], k4 = wk4[c], o4 = ow4[c];
            aK = fmaf(s4.x, k4.x, aK); aK = fmaf(s4.y, k4.y, aK);
            aK = fmaf(s4.z, k4.z, aK); aK = fmaf(s4.w, k4.w, aK);
            aM = fmaf(s4.x, o4.x, aM); aM = fmaf(s4.y, o4.y, aM);
            aM = fmaf(s4.z, o4.z, aM); aM = fmaf(s4.w, o4.w, aM);
        }
        pK[part][d] = aK;
        pM[part][d] = aM;
    }
    __syncthreads();
    if (part == 0) {
        kv[d]        = Wk_b[d] + pK[0][d] + pK[1][d] + pK[2][d] + pK[3][d];
        g_M[b][j][d] = pM[0][d] + pM[1][d] + pM[2][d] + pM[3][d];
    }
    __syncthreads();

    {
        float a = 0.f;
        const int dd0 = part * 16;
        #pragma unroll
        for (int k = 0; k < 16; ++k)
            a = fmaf(Wq_w[(size_t)(dd0 + k) * DD + d], kv[dd0 + k], a);
        pK[part][d] = a;
    }
    __syncthreads();
    if (part == 0)
        g_ck[b][j][d] = 0.125f * (pK[0][d] + pK[1][d] + pK[2][d] + pK[3][d]);
    if (tid == 64) {
        float a = 0.f;
        #pragma unroll 8
        for (int dd = 0; dd < DD; ++dd)
            a = fmaf(Wq_b[dd], kv[dd], a);
        g_c0[b][j] = a * 0.125f;
    }
    if (b == 0 && j == 0 && tid == 0) g_sscale = expf(density_scale[0]);
}

// ---------------- main per-point kernel (monolith, wbuf aliased, 6 CTAs) ----------------
__global__ void __launch_bounds__(BLK, 6)
points_kernel(const float* __restrict__ x,
              const float* __restrict__ coor,
              float* __restrict__ xo,
              float* __restrict__ wout,
              float* __restrict__ sig,
              const float* __restrict__ out_b,
              int Npts)
{
    __shared__ float4 xs4[TILE * 16];          // 32 KB (aliased as wbuf after phase B)
    __shared__ float4 sCK4[NSLOT * 16];        // 2.25 KB
    __shared__ float  sC0[NSLOT];
    __shared__ float  sScale;

    float* wbuf = (float*)xs4;                 // stride-12 [pt][0..8,pad3], 6 KB alias

    const int b     = blockIdx.y;
    const int t     = threadIdx.x;
    const int tile0 = blockIdx.x * TILE;
    const int valid = min(TILE, Npts - tile0);
    const size_t base = (size_t)b * Npts + tile0;

    // prefetch coor early (latency hidden behind staging loop)
    float cx = 0.f, cy = 0.f, cz = 0.f;
    if (t < valid) {
        const float* cp = coor + (base + t) * 3;
        cx = cp[0]; cy = cp[1]; cz = cp[2];
    }

    {
        const float4* gck = (const float4*)&g_ck[b][0][0];
        for (int i = t; i < NSLOT * 16; i += BLK) sCK4[i] = gck[i];
        if (t < NSLOT) sC0[t] = g_c0[b][t];
        if (t == 0)    sScale = g_sscale;
    }

    // ---- phase A: stage x tile (coalesced LDG, swizzled STS) ----
    {
        const float4* gx = (const float4*)(x + base * DD);
        #pragma unroll
        for (int kk = 0; kk < 16; ++kk) {
            int i   = kk * BLK + t;
            int row = i >> 4, ch = i & 15;
            if (row < valid)
                xs4[(row << 4) | (ch ^ (row & 7))] = gx[i];
        }
    }
    __syncthreads();

    // ---- phase B: logits + softmax, 1 point/thread (all 4 SMSPs) ----
    float wv[NSLOT];
    float sg = 0.f;
    const bool active = (t < valid);
    if (active) {
        u64 acc[NSLOT];
        #pragma unroll
        for (int j = 0; j < NSLOT; ++j) acc[j] = 0ull;

        const float4* xr = &xs4[t << 4];
        const int sw = t & 7;
        #pragma unroll
        for (int c = 0; c < 16; ++c) {
            u64 xlo, xhi;
            lds128(xlo, xhi, &xr[c ^ sw]);
            #pragma unroll
            for (int j = 0; j < NSLOT; ++j) {
                u64 clo, chi;
                lds128(clo, chi, &sCK4[j * 16 + c]);
                acc[j] = ffma2(xlo, clo, acc[j]);
                acc[j] = ffma2(xhi, chi, acc[j]);
            }
        }
        float lg[NSLOT];
        #pragma unroll
        for (int j = 0; j < NSLOT; ++j) {
            float lo, hi; unpack2(acc[j], lo, hi);
            lg[j] = lo + hi + sC0[j];
        }

        bool oob = (fabsf(cx) > 1.0f) || (fabsf(cy) > 1.0f) || (fabsf(cz) > 1.0f);
        const int kmax = oob ? 2 : NSLOT;

        float m = fmaxf(lg[0], lg[1]);
        if (!oob) {
            #pragma unroll
            for (int j = 2; j < NSLOT; ++j) m = fmaxf(m, lg[j]);
        }
        float sum = 0.f;
        #pragma unroll
        for (int j = 0; j < NSLOT; ++j) {
            float e = (j < kmax) ? __expf(lg[j] - m) : 0.f;
            wv[j] = e; sum += e;
        }
        const float inv = __frcp_rn(sum);
        #pragma unroll
        for (int j = 1; j < NSLOT; ++j)
            sg = fmaf(fmaxf(lg[j], 0.f), wv[j], sg);
        sg *= inv * sScale;
        #pragma unroll
        for (int j = 0; j < NSLOT; ++j) wv[j] *= inv;
    }
    __syncthreads();            // all xs reads complete -> alias becomes safe

    if (active) {
        sig[base + t] = sg;
        float* wp = &wbuf[t * 12];
        ((float4*)wp)[0] = make_float4(wv[0], wv[1], wv[2], wv[3]);
        ((float4*)wp)[1] = make_float4(wv[4], wv[5], wv[6], wv[7]);
        ((float4*)wp)[2] = make_float4(wv[8], 0.f, 0.f, 0.f);
    }
    __syncthreads();

    // ---- phase C: xo = w @ M + out_b; also emit w to global ----
    {
        const int g  = t >> 4;     // 0..7 : group of 16 points
        const int ch = t & 15;     // f4 chunk of the 64-float row
        u64 Mlo[NSLOT], Mhi[NSLOT];
        #pragma unroll
        for (int j = 0; j < NSLOT; ++j) {
            float4 mv = ((const float4*)&g_M[b][j][0])[ch];
            Mlo[j] = pack2(mv.x, mv.y);
            Mhi[j] = pack2(mv.z, mv.w);
        }
        float4 obv = ((const float4*)out_b)[ch];
        const u64 oblo = pack2(obv.x, obv.y), obhi = pack2(obv.z, obv.w);

        float4* go = (float4*)(xo + base * DD);
        float*  gw = wout + base * (size_t)NSLOT;
        #pragma unroll 4
        for (int i = 0; i < 16; ++i) {
            int pt = g * 16 + i;
            if (pt < valid) {
                const float* wp = &wbuf[pt * 12];
                u64 w01, w23, w45, w67;
                lds128(w01, w23, wp);
                lds128(w45, w67, wp + 4);
                float w0,w1,w2,w3,w4,w5,w6,w7;
                unpack2(w01, w0, w1); unpack2(w23, w2, w3);
                unpack2(w45, w4, w5); unpack2(w67, w6, w7);
                float w8 = wp[8];
                float wreg[NSLOT] = {w0,w1,w2,w3,w4,w5,w6,w7,w8};

                u64 olo = oblo, ohi = obhi;
                #pragma unroll
                for (int j = 0; j < NSLOT; ++j) {
                    u64 wj = pack2dup(wreg[j]);
                    olo = ffma2(wj, Mlo[j], olo);
                    ohi = ffma2(wj, Mhi[j], ohi);
                }
                float4 o;
                unpack2(olo, o.x, o.y);
                unpack2(ohi, o.z, o.w);
                go[pt * 16 + ch] = o;                 // lanes 0-15 one row: coalesced

                if (ch < NSLOT)
                    gw[(size_t)pt * NSLOT + ch] = wreg[ch];
            }
        }
    }
}

extern "C" void kernel_launch(void* const* d_in, const int* in_sizes, int n_in,
                              void* d_out, int out_size)
{
    const float* point_feats   = (const float*)d_in[0];
    // d_in[1] = points_emb (unused by the scored block)
    const float* slots         = (const float*)d_in[2];
    const float* coor          = (const float*)d_in[3];
    const float* empty_slot    = (const float*)d_in[4];
    const float* Wq_w          = (const float*)d_in[5];
    const float* Wq_b          = (const float*)d_in[6];
    const float* Wk_w          = (const float*)d_in[7];
    const float* Wk_b          = (const float*)d_in[8];
    const float* out_w         = (const float*)d_in[9];
    const float* out_b         = (const float*)d_in[10];
    const float* density_scale = (const float*)d_in[11];

    const int B    = in_sizes[2] / (8 * 64);      // slots: [B, 8, 64]
    const int Npts = in_sizes[0] / (B * 64);      // point_feats: [B, N, 64]

    float* xo   = (float*)d_out;                                  // [B, N, 64]
    float* wout = xo + (size_t)B * Npts * 64;                     // [B, N, 9]
    float* sg   = wout + (size_t)B * Npts * 9;                    // [B, N]

    dim3 pgrid(NSLOT, B);
    precompute_kernel<<<pgrid, 256>>>(slots, empty_slot, Wq_w, Wq_b,
                                      Wk_w, Wk_b, out_w, density_scale);

    dim3 grid((Npts + TILE - 1) / TILE, B);
    points_kernel<<<grid, BLK>>>(point_feats, coor, xo, wout, sg, out_b, Npts);
}